// round 3
// baseline (speedup 1.0000x reference)
#include <cuda_runtime.h>

// Direct conv NCHW fp32, SIMT baseline tuned to be FFMA-issue-bound.
// x: [32,128,56,56], w: [256,128,3,3] (OIHW), out: [32,256,56,56]
// stride 1, pad 1.
//
// Block: 64 oc x (8x8) spatial x 1 image. 256 threads.
// Thread: 4 oc x 4 pixel register tile (16 accumulators).
// Input channels processed in chunks of 8 staged in shared memory.

#define CC       8     // input-channel chunk
#define TILE_OC  64
#define TH       8
#define TW       8
#define CIN      128
#define COUT     256
#define HW       56

__global__ __launch_bounds__(256, 6)
void conv3x3_simt_kernel(const float* __restrict__ x,
                         const float* __restrict__ w,
                         float* __restrict__ out)
{
    // input tile: CC x 10 x 10 (halo of 1 each side), pitch 10 (conflict-free: two
    // 8-wide rows 10 banks apart never collide)
    __shared__ float s_in[CC * 10 * 10];
    // weights: [cc][rs][oc], oc fastest -> compute reads are aligned float4,
    // fill stores (oc = lane) are conflict-free
    __shared__ float s_w[CC * 9 * TILE_OC];

    const int tid = threadIdx.x;
    const int n   = blockIdx.z;
    const int oc0 = blockIdx.y * TILE_OC;
    const int th0 = (blockIdx.x / (HW / TW)) * TH;
    const int tw0 = (blockIdx.x % (HW / TW)) * TW;

    const int tk = tid >> 4;   // 0..15 : oc group (4 oc each)
    const int tp = tid & 15;   // 0..15 : pixel group (4 strided pixels each)

    float acc[4][4];
#pragma unroll
    for (int a = 0; a < 4; a++)
#pragma unroll
        for (int b = 0; b < 4; b++) acc[a][b] = 0.f;

    const float* xn = x + (long)n * CIN * HW * HW;

    for (int c0 = 0; c0 < CIN; c0 += CC) {
        __syncthreads();   // protect smem from previous chunk's readers

        // ---- stage input tile: CC x 10 x 10 = 800 floats, zero-padded halo ----
        for (int idx = tid; idx < CC * 100; idx += 256) {
            int cc  = idx / 100;
            int rem = idx - cc * 100;
            int iy  = rem / 10;
            int ix  = rem - iy * 10;
            int y   = th0 - 1 + iy;
            int xx  = tw0 - 1 + ix;
            float v = 0.f;
            if ((unsigned)y < (unsigned)HW && (unsigned)xx < (unsigned)HW)
                v = xn[((c0 + cc) * HW + y) * HW + xx];
            s_in[idx] = v;
        }

        // ---- stage weights: CC x 9 x 64 = 4608 floats ----
        // smem idx: oc fastest (lane==oc -> conflict-free STS).
        // global:   OIHW, stride over oc is CIN*9; weights are L2-resident (1.2 MB).
        for (int idx = tid; idx < CC * 9 * TILE_OC; idx += 256) {
            int oc  = idx & (TILE_OC - 1);
            int rsc = idx >> 6;            // cc*9 + rs
            int cc  = rsc / 9;
            int rs  = rsc - cc * 9;
            s_w[idx] = w[(long)(oc0 + oc) * (CIN * 9) + (c0 + cc) * 9 + rs];
        }
        __syncthreads();

        // ---- compute: 8 cc x 9 taps x 4x4 register tile ----
#pragma unroll 2
        for (int cc = 0; cc < CC; cc++) {
#pragma unroll
            for (int rs = 0; rs < 9; rs++) {
                const int r = rs / 3, s = rs - 3 * r;
                float4 wv = *(const float4*)&s_w[(cc * 9 + rs) * TILE_OC + tk * 4];
#pragma unroll
                for (int b = 0; b < 4; b++) {
                    int pix = tp + 16 * b;           // 0..63 strided -> coalesced stores
                    int ph  = pix >> 3, pw = pix & 7;
                    float iv = s_in[cc * 100 + (ph + r) * 10 + (pw + s)];
                    acc[0][b] += wv.x * iv;
                    acc[1][b] += wv.y * iv;
                    acc[2][b] += wv.z * iv;
                    acc[3][b] += wv.w * iv;
                }
            }
        }
    }

    // ---- store 4x4 tile ----
#pragma unroll
    for (int a = 0; a < 4; a++) {
        const int oc = oc0 + tk * 4 + a;
        float* outc = out + (((long)n * COUT + oc) * HW + th0) * HW + tw0;
#pragma unroll
        for (int b = 0; b < 4; b++) {
            int pix = tp + 16 * b;
            int ph  = pix >> 3, pw = pix & 7;
            outc[ph * HW + pw] = acc[a][b];
        }
    }
}

extern "C" void kernel_launch(void* const* d_in, const int* in_sizes, int n_in,
                              void* d_out, int out_size)
{
    const float* x = (const float*)d_in[0];   // [32,128,56,56]
    const float* w = (const float*)d_in[1];   // [256,128,3,3]
    float* out     = (float*)d_out;           // [32,256,56,56]

    dim3 grid((HW / TH) * (HW / TW),  // 49 spatial tiles
              COUT / TILE_OC,         // 4 oc tiles
              32);                    // batch
    conv3x3_simt_kernel<<<grid, 256>>>(x, w, out);
}

// round 5
// speedup vs baseline: 5.7562x; 5.7562x over previous
#include <cuda_runtime.h>
#include <cuda_bf16.h>
#include <cstdint>

// Conv 3x3 s1 p1, NCHW fp32: x[32,128,56,56] * w[256,128,3,3] -> out[32,256,56,56]
// Implicit GEMM on mma.sync bf16 (HMMA; tcgen05 is unusable: harness PTX target
// is sm_103 without the 'a' feature, which gates all tcgen05/TMA instructions).
// fp32 accuracy via bf16 3-split: C = Ah*Bh + Al*Bh + Ah*Bl.
//   M = 128-pixel strip over padded 58-pitch grid (tap shifts = plain offsets)
//   N = 256 output channels (all in one CTA -> weights staged once per chunk)
//   K = 1152 = 9 taps x 128 c, chunked by 64 (= one 128B SW128 row)

#define QP     3520
#define CIN    128
#define COUT   256
#define NIMG   32
#define NSTRIP 26          // 26*128 = 3328 >= last valid q 3245
#define NCHUNK 18

// ---------------- device scratch (static = allowed) ----------------
__device__ __align__(256) __nv_bfloat16 g_xhi[(size_t)NIMG * QP * CIN];
__device__ __align__(256) __nv_bfloat16 g_xlo[(size_t)NIMG * QP * CIN];
__device__ __align__(256) __nv_bfloat16 g_whi[9 * COUT * CIN];
__device__ __align__(256) __nv_bfloat16 g_wlo[9 * COUT * CIN];

// ---------------- helpers ----------------
__device__ __forceinline__ uint32_t smem_u32(const void* p) {
    uint32_t a;
    asm("{ .reg .u64 t; cvta.to.shared.u64 t, %1; cvt.u32.u64 %0, t; }" : "=r"(a) : "l"(p));
    return a;
}
#define SWZ128(o) ((o) ^ (((o) >> 3) & 0x70))

__device__ __forceinline__ void cpa16(uint32_t saddr, const void* gptr) {
    asm volatile("cp.async.cg.shared.global [%0], [%1], 16;"
                 :: "r"(saddr), "l"(__cvta_generic_to_global(gptr)) : "memory");
}
__device__ __forceinline__ void ldsm4(uint32_t* r, uint32_t a) {
    asm volatile("ldmatrix.sync.aligned.m8n8.x4.shared.b16 {%0,%1,%2,%3}, [%4];"
                 : "=r"(r[0]), "=r"(r[1]), "=r"(r[2]), "=r"(r[3]) : "r"(a));
}
__device__ __forceinline__ void mma16816(float* c, const uint32_t* a, const uint32_t* b) {
    asm volatile("mma.sync.aligned.m16n8k16.row.col.f32.bf16.bf16.f32 "
                 "{%0,%1,%2,%3},{%4,%5,%6,%7},{%8,%9},{%0,%1,%2,%3};"
                 : "+f"(c[0]), "+f"(c[1]), "+f"(c[2]), "+f"(c[3])
                 : "r"(a[0]), "r"(a[1]), "r"(a[2]), "r"(a[3]), "r"(b[0]), "r"(b[1]));
}

// ---------------- pre-pass: x -> padded NHWC bf16 hi/lo ----------------
__global__ __launch_bounds__(256) void prep_x(const float* __restrict__ x) {
    __shared__ float sx[CIN * 56];
    const int yp = blockIdx.x;          // 0..57 padded row
    const int n  = blockIdx.y;
    const int tid = threadIdx.x;
    const bool rowvalid = (yp >= 1 && yp <= 56);
    if (rowvalid) {
        const int y = yp - 1;
        for (int idx = tid; idx < CIN * 56; idx += 256) {
            int c = idx / 56, xx = idx - c * 56;
            sx[idx] = x[(((size_t)n * CIN + c) * 56 + y) * 56 + xx];
        }
    }
    __syncthreads();
    for (int idx = tid; idx < 58 * CIN; idx += 256) {
        int xp = idx >> 7, c = idx & 127;
        float v = 0.f;
        if (rowvalid && xp >= 1 && xp <= 56) v = sx[c * 56 + (xp - 1)];
        __nv_bfloat16 h = __float2bfloat16(v);
        __nv_bfloat16 l = __float2bfloat16(v - __bfloat162float(h));
        size_t o = ((size_t)n * QP + yp * 58 + xp) * CIN + c;
        g_xhi[o] = h;
        g_xlo[o] = l;
    }
}

// ---------------- pre-pass: w -> [tap][oc][c] bf16 hi/lo ----------------
__global__ __launch_bounds__(256) void prep_w(const float* __restrict__ w) {
    int idx = blockIdx.x * 256 + threadIdx.x;       // 9*256*128
    if (idx < 9 * COUT * CIN) {
        int tap = idx / (COUT * CIN);
        int rem = idx - tap * (COUT * CIN);
        int oc = rem >> 7, c = rem & 127;
        float v = w[((size_t)(oc * CIN + c)) * 9 + tap];
        __nv_bfloat16 h = __float2bfloat16(v);
        __nv_bfloat16 l = __float2bfloat16(v - __bfloat162float(h));
        g_whi[idx] = h;
        g_wlo[idx] = l;
    }
}

// ---------------- main GEMM ----------------
// stage buffer (96KB): A_hi 16K | A_lo 16K | B_hi 32K | B_lo 32K, SW128 rows of 128B
#define SM_STAGE 98304
#define SM_TOTAL (2 * SM_STAGE)

__global__ __launch_bounds__(512, 1) void conv_mma(float* __restrict__ out) {
    extern __shared__ char smem[];
    const uint32_t sb = smem_u32(smem);
    const int tid = threadIdx.x, lane = tid & 31, wid = tid >> 5;
    const int strip = blockIdx.x, n_img = blockIdx.y;
    const int Q0 = strip * 128;
    const int Mb = (wid & 3) * 32;   // warp M base (pixels)
    const int Nb = (wid >> 2) * 64;  // warp N base (oc)

    float acc[2][8][4];
#pragma unroll
    for (int i = 0; i < 2; i++)
#pragma unroll
        for (int j = 0; j < 8; j++)
#pragma unroll
            for (int k = 0; k < 4; k++) acc[i][j][k] = 0.f;

    const size_t xbase = (size_t)n_img * QP * CIN;

    auto stage = [&](int chunk, int b) {
        const int tap = chunk >> 1, c0 = (chunk & 1) * 64;
        const int offq = (tap / 3) * 58 + (tap % 3);
        const uint32_t s0 = sb + b * SM_STAGE;
        const size_t abase = xbase + (size_t)(Q0 + offq) * CIN + c0;
        for (int idx = tid; idx < 1024; idx += 512) {      // A: 128 rows x 4x16B
            int m = idx >> 3, t = idx & 7;
            size_t g = abase + (size_t)m * CIN + t * 8;
            uint32_t so = SWZ128((uint32_t)(m * 128 + t * 16));
            cpa16(s0 + so,         g_xhi + g);
            cpa16(s0 + 16384 + so, g_xlo + g);
        }
        const size_t bbase = (size_t)tap * COUT * CIN + c0;
        for (int idx = tid; idx < 2048; idx += 512) {      // B: 256 rows x 4x16B
            int oc = idx >> 3, t = idx & 7;
            size_t g = bbase + (size_t)oc * CIN + t * 8;
            uint32_t so = SWZ128((uint32_t)(oc * 128 + t * 16));
            cpa16(s0 + 32768 + so, g_whi + g);
            cpa16(s0 + 65536 + so, g_wlo + g);
        }
        asm volatile("cp.async.commit_group;" ::: "memory");
    };

    // per-lane ldmatrix address components
    const uint32_t a_row = Mb + (lane & 15);
    const uint32_t a_kb  = (lane >> 4) * 16;
    const uint32_t b_row = Nb + (lane & 7) + ((lane >> 4) << 3);
    const uint32_t b_kb  = ((lane >> 3) & 1) * 16;

    stage(0, 0);
    for (int i = 0; i < NCHUNK; i++) {
        const int b = i & 1;
        if (i + 1 < NCHUNK) {
            stage(i + 1, b ^ 1);
            asm volatile("cp.async.wait_group 1;" ::: "memory");
        } else {
            asm volatile("cp.async.wait_group 0;" ::: "memory");
        }
        __syncthreads();

        const uint32_t sA_hi = sb + b * SM_STAGE;
        const uint32_t sA_lo = sA_hi + 16384;
        const uint32_t sB_hi = sA_hi + 32768;
        const uint32_t sB_lo = sA_hi + 65536;

#pragma unroll
        for (int ks = 0; ks < 4; ks++) {
            uint32_t ah[2][4], al[2][4], bb[4][4];
#pragma unroll
            for (int mt = 0; mt < 2; mt++) {
                uint32_t off = SWZ128((a_row + mt * 16) * 128 + ks * 32 + a_kb);
                ldsm4(ah[mt], sA_hi + off);
                ldsm4(al[mt], sA_lo + off);
            }
            // Bh: used by both Ah and Al products
#pragma unroll
            for (int np = 0; np < 4; np++) {
                uint32_t off = SWZ128((b_row + np * 16) * 128 + ks * 32 + b_kb);
                ldsm4(bb[np], sB_hi + off);
            }
#pragma unroll
            for (int mt = 0; mt < 2; mt++)
#pragma unroll
                for (int np = 0; np < 4; np++) {
                    mma16816(acc[mt][np * 2],     ah[mt], bb[np]);
                    mma16816(acc[mt][np * 2 + 1], ah[mt], bb[np] + 2);
                    mma16816(acc[mt][np * 2],     al[mt], bb[np]);
                    mma16816(acc[mt][np * 2 + 1], al[mt], bb[np] + 2);
                }
            // Bl: with Ah only
#pragma unroll
            for (int np = 0; np < 4; np++) {
                uint32_t off = SWZ128((b_row + np * 16) * 128 + ks * 32 + b_kb);
                ldsm4(bb[np], sB_lo + off);
            }
#pragma unroll
            for (int mt = 0; mt < 2; mt++)
#pragma unroll
                for (int np = 0; np < 4; np++) {
                    mma16816(acc[mt][np * 2],     ah[mt], bb[np]);
                    mma16816(acc[mt][np * 2 + 1], ah[mt], bb[np] + 2);
                }
        }
        __syncthreads();
    }

    // ---- epilogue: registers -> NCHW out ----
#pragma unroll
    for (int mt = 0; mt < 2; mt++) {
        const int m0 = Mb + mt * 16 + (lane >> 2);
#pragma unroll
        for (int nt = 0; nt < 8; nt++) {
            const int n0 = Nb + nt * 8 + (lane & 3) * 2;
            const size_t ob = ((size_t)n_img * COUT + n0) * 3136;
            int q = Q0 + m0;
            int y = q / 58, x = q - y * 58;
            if (y < 56 && x < 56) {
                size_t o = ob + y * 56 + x;
                out[o]        = acc[mt][nt][0];
                out[o + 3136] = acc[mt][nt][1];
            }
            q += 8;
            y = q / 58; x = q - y * 58;
            if (y < 56 && x < 56) {
                size_t o = ob + y * 56 + x;
                out[o]        = acc[mt][nt][2];
                out[o + 3136] = acc[mt][nt][3];
            }
        }
    }
}

// ---------------- launch ----------------
extern "C" void kernel_launch(void* const* d_in, const int* in_sizes, int n_in,
                              void* d_out, int out_size) {
    const float* x = (const float*)d_in[0];   // [32,128,56,56]
    const float* w = (const float*)d_in[1];   // [256,128,3,3]
    float* out = (float*)d_out;               // [32,256,56,56]

    static bool attr_set = false;
    if (!attr_set) {
        cudaFuncSetAttribute(conv_mma, cudaFuncAttributeMaxDynamicSharedMemorySize, SM_TOTAL);
        attr_set = true;
    }

    prep_x<<<dim3(58, NIMG), 256>>>(x);
    prep_w<<<(9 * COUT * CIN + 255) / 256, 256>>>(w);
    conv_mma<<<dim3(NSTRIP, NIMG), 512, SM_TOTAL>>>(out);
}

// round 6
// speedup vs baseline: 12.5017x; 2.1719x over previous
#include <cuda_runtime.h>
#include <cuda_fp16.h>
#include <cstdint>

// Conv 3x3 s1 p1, NCHW fp32: x[32,128,56,56] * w[256,128,3,3] -> out[32,256,56,56]
// Implicit GEMM on mma.sync m16n8k16 fp16 (fp32 accum), single pass.
// (tcgen05/TMA unusable: harness PTX target is sm_103 without 'a'.)
//   M = 128-pixel strip over padded 58-pitch grid (tap shifts = plain offsets)
//   N = 256 output channels
//   K = 1152 = 9 taps x 128 c, chunked by 64 (one 128B SW128 row of fp16)
// 256 threads = 8 warps, each computing a 64x64 register tile (128 fp32 acc).

#define QP     3520
#define CIN    128
#define COUT   256
#define NIMG   32
#define NSTRIP 26
#define NCHUNK 18

// ---------------- device scratch (static = allowed) ----------------
__device__ __align__(256) __half g_xh[(size_t)NIMG * QP * CIN];
__device__ __align__(256) __half g_wh[9 * COUT * CIN];

// ---------------- helpers ----------------
__device__ __forceinline__ uint32_t smem_u32(const void* p) {
    uint32_t a;
    asm("{ .reg .u64 t; cvta.to.shared.u64 t, %1; cvt.u32.u64 %0, t; }" : "=r"(a) : "l"(p));
    return a;
}
#define SWZ128(o) ((o) ^ (((o) >> 3) & 0x70))

__device__ __forceinline__ void cpa16(uint32_t saddr, const void* gptr) {
    asm volatile("cp.async.cg.shared.global [%0], [%1], 16;"
                 :: "r"(saddr), "l"(__cvta_generic_to_global(gptr)) : "memory");
}
__device__ __forceinline__ void ldsm4(uint32_t* r, uint32_t a) {
    asm volatile("ldmatrix.sync.aligned.m8n8.x4.shared.b16 {%0,%1,%2,%3}, [%4];"
                 : "=r"(r[0]), "=r"(r[1]), "=r"(r[2]), "=r"(r[3]) : "r"(a));
}
__device__ __forceinline__ void mma16816(float* c, const uint32_t* a, const uint32_t* b) {
    asm volatile("mma.sync.aligned.m16n8k16.row.col.f32.f16.f16.f32 "
                 "{%0,%1,%2,%3},{%4,%5,%6,%7},{%8,%9},{%0,%1,%2,%3};"
                 : "+f"(c[0]), "+f"(c[1]), "+f"(c[2]), "+f"(c[3])
                 : "r"(a[0]), "r"(a[1]), "r"(a[2]), "r"(a[3]), "r"(b[0]), "r"(b[1]));
}

// ---------------- pre-pass: x -> padded NHWC fp16 ----------------
__global__ __launch_bounds__(256) void prep_x(const float* __restrict__ x) {
    __shared__ float sx[CIN * 56];
    const int yp = blockIdx.x;          // 0..57 padded row
    const int n  = blockIdx.y;
    const int tid = threadIdx.x;
    const bool rowvalid = (yp >= 1 && yp <= 56);
    if (rowvalid) {
        const int y = yp - 1;
        for (int idx = tid; idx < CIN * 56; idx += 256) {
            int c = idx / 56, xx = idx - c * 56;
            sx[idx] = x[(((size_t)n * CIN + c) * 56 + y) * 56 + xx];
        }
    }
    __syncthreads();
    // each thread writes one half2 (two channels): 58*64 items
    for (int idx = tid; idx < 58 * 64; idx += 256) {
        int xp = idx >> 6, cp = (idx & 63) * 2;
        float v0 = 0.f, v1 = 0.f;
        if (rowvalid && xp >= 1 && xp <= 56) {
            v0 = sx[cp * 56 + (xp - 1)];
            v1 = sx[(cp + 1) * 56 + (xp - 1)];
        }
        __half2 h = __floats2half2_rn(v0, v1);
        size_t o = ((size_t)n * QP + yp * 58 + xp) * CIN + cp;
        *(__half2*)(g_xh + o) = h;
    }
}

// ---------------- pre-pass: w -> [tap][oc][c] fp16 ----------------
__global__ __launch_bounds__(256) void prep_w(const float* __restrict__ w) {
    int idx = blockIdx.x * 256 + threadIdx.x;       // 9*256*64 half2 items
    if (idx < 9 * COUT * 64) {
        int tap = idx / (COUT * 64);
        int rem = idx - tap * (COUT * 64);
        int oc = rem >> 6, cp = (rem & 63) * 2;
        float v0 = w[((size_t)(oc * CIN + cp)) * 9 + tap];
        float v1 = w[((size_t)(oc * CIN + cp + 1)) * 9 + tap];
        size_t o = ((size_t)tap * COUT + oc) * CIN + cp;
        *(__half2*)(g_wh + o) = __floats2half2_rn(v0, v1);
    }
}

// ---------------- main GEMM ----------------
// stage (48KB): A 16K (128 rows x 128B) | B 32K (256 rows x 128B), SW128
#define SM_STAGE 49152
#define SM_TOTAL (2 * SM_STAGE)

__global__ __launch_bounds__(256, 1) void conv_mma(float* __restrict__ out) {
    extern __shared__ char smem[];
    const uint32_t sb = smem_u32(smem);
    const int tid = threadIdx.x, lane = tid & 31, wid = tid >> 5;
    const int strip = blockIdx.x, n_img = blockIdx.y;
    const int Q0 = strip * 128;
    const int Mb = (wid & 1) * 64;   // warp M base
    const int Nb = (wid >> 1) * 64;  // warp N base

    float acc[4][8][4];
#pragma unroll
    for (int i = 0; i < 4; i++)
#pragma unroll
        for (int j = 0; j < 8; j++)
#pragma unroll
            for (int k = 0; k < 4; k++) acc[i][j][k] = 0.f;

    const size_t xbase = (size_t)n_img * QP * CIN;

    auto stage = [&](int chunk, int b) {
        const int tap = chunk >> 1, c0 = (chunk & 1) * 64;
        const int offq = (tap / 3) * 58 + (tap % 3);
        const uint32_t s0 = sb + b * SM_STAGE;
        const size_t abase = xbase + (size_t)(Q0 + offq) * CIN + c0;
#pragma unroll
        for (int idx = tid; idx < 1024; idx += 256) {      // A: 128 rows x 8x16B
            int m = idx >> 3, t = idx & 7;
            cpa16(s0 + SWZ128((uint32_t)(m * 128 + t * 16)),
                  g_xh + abase + (size_t)m * CIN + t * 8);
        }
        const size_t bbase = (size_t)tap * COUT * CIN + c0;
#pragma unroll
        for (int idx = tid; idx < 2048; idx += 256) {      // B: 256 rows x 8x16B
            int oc = idx >> 3, t = idx & 7;
            cpa16(s0 + 16384 + SWZ128((uint32_t)(oc * 128 + t * 16)),
                  g_wh + bbase + (size_t)oc * CIN + t * 8);
        }
        asm volatile("cp.async.commit_group;" ::: "memory");
    };

    // per-lane ldmatrix address components
    const uint32_t a_row = Mb + (lane & 15);
    const uint32_t a_kb  = (lane >> 4) * 16;
    const uint32_t b_row = Nb + (lane & 7) + ((lane >> 4) << 3);
    const uint32_t b_kb  = ((lane >> 3) & 1) * 16;

    stage(0, 0);
    for (int i = 0; i < NCHUNK; i++) {
        const int b = i & 1;
        if (i + 1 < NCHUNK) {
            stage(i + 1, b ^ 1);
            asm volatile("cp.async.wait_group 1;" ::: "memory");
        } else {
            asm volatile("cp.async.wait_group 0;" ::: "memory");
        }
        __syncthreads();

        const uint32_t sA = sb + b * SM_STAGE;
        const uint32_t sB = sA + 16384;

#pragma unroll
        for (int ks = 0; ks < 4; ks++) {
            uint32_t af[4][4], bf[4][4];
#pragma unroll
            for (int mt = 0; mt < 4; mt++)
                ldsm4(af[mt], sA + SWZ128((a_row + mt * 16) * 128 + ks * 32 + a_kb));
#pragma unroll
            for (int np = 0; np < 4; np++)
                ldsm4(bf[np], sB + SWZ128((b_row + np * 16) * 128 + ks * 32 + b_kb));
#pragma unroll
            for (int mt = 0; mt < 4; mt++)
#pragma unroll
                for (int np = 0; np < 4; np++) {
                    mma16816(acc[mt][np * 2],     af[mt], bf[np]);
                    mma16816(acc[mt][np * 2 + 1], af[mt], bf[np] + 2);
                }
        }
        __syncthreads();
    }

    // ---- epilogue: registers -> NCHW out ----
#pragma unroll
    for (int mt = 0; mt < 4; mt++) {
        const int m0 = Mb + mt * 16 + (lane >> 2);
#pragma unroll
        for (int nt = 0; nt < 8; nt++) {
            const int n0 = Nb + nt * 8 + (lane & 3) * 2;
            const size_t ob = ((size_t)n_img * COUT + n0) * 3136;
            int q = Q0 + m0;
            int y = q / 58, x = q - y * 58;
            if (y < 56 && x < 56) {
                size_t o = ob + y * 56 + x;
                out[o]        = acc[mt][nt][0];
                out[o + 3136] = acc[mt][nt][1];
            }
            q += 8;
            y = q / 58; x = q - y * 58;
            if (y < 56 && x < 56) {
                size_t o = ob + y * 56 + x;
                out[o]        = acc[mt][nt][2];
                out[o + 3136] = acc[mt][nt][3];
            }
        }
    }
}

// ---------------- launch ----------------
extern "C" void kernel_launch(void* const* d_in, const int* in_sizes, int n_in,
                              void* d_out, int out_size) {
    const float* x = (const float*)d_in[0];   // [32,128,56,56]
    const float* w = (const float*)d_in[1];   // [256,128,3,3]
    float* out = (float*)d_out;               // [32,256,56,56]

    static bool attr_set = false;
    if (!attr_set) {
        cudaFuncSetAttribute(conv_mma, cudaFuncAttributeMaxDynamicSharedMemorySize, SM_TOTAL);
        attr_set = true;
    }

    prep_x<<<dim3(58, NIMG), 256>>>(x);
    prep_w<<<(9 * COUT * 64 + 255) / 256, 256>>>(w);
    conv_mma<<<dim3(NSTRIP, NIMG), 256, SM_TOTAL>>>(out);
}

// round 7
// speedup vs baseline: 14.5990x; 1.1678x over previous
#include <cuda_runtime.h>
#include <cuda_fp16.h>
#include <cstdint>

// Conv 3x3 s1 p1, NCHW fp32: x[32,128,56,56] * w[256,128,3,3] -> out[32,256,56,56]
// Implicit GEMM on mma.sync m16n8k16 fp16 (fp32 accum).
//   Per CTA: M=256 pixel strip, N=128 oc, K=1152 (9 taps x 128c).
//   A: whole padded strip (384 rows x 256B) resident in smem, staged ONCE;
//      each tap's A tile is a view at row offset offq -> 9x less A staging.
//   B: 32KB per tap, double-buffered cp.async.
// Row-relative swizzle: 16B column t stored at (t ^ (row&7)) -> conflict-free
// ldmatrix at arbitrary row offsets.

#define QP     3520
#define CIN    128
#define COUT   256
#define NIMG   32
#define NSTRIP 13          // 13*256 = 3328 >= last valid q 3245
#define AROWS  384         // 256 + max tap offset 118, rounded up
#define SMA    (AROWS * 256)
#define SMB    32768
#define SM_TOTAL (SMA + 2 * SMB)   // 163840

// ---------------- device scratch (static = allowed) ----------------
__device__ __align__(256) __half g_xh[(size_t)NIMG * QP * CIN];
__device__ __align__(256) __half g_wh[9 * COUT * CIN];

// ---------------- helpers ----------------
__device__ __forceinline__ uint32_t smem_u32(const void* p) {
    uint32_t a;
    asm("{ .reg .u64 t; cvta.to.shared.u64 t, %1; cvt.u32.u64 %0, t; }" : "=r"(a) : "l"(p));
    return a;
}
__device__ __forceinline__ uint32_t swz(int row, int t) {
    return (uint32_t)(row * 256 + ((t ^ (row & 7)) << 4));
}
__device__ __forceinline__ void cpa16(uint32_t saddr, const void* gptr) {
    asm volatile("cp.async.cg.shared.global [%0], [%1], 16;"
                 :: "r"(saddr), "l"(__cvta_generic_to_global(gptr)) : "memory");
}
__device__ __forceinline__ void ldsm4(uint32_t* r, uint32_t a) {
    asm volatile("ldmatrix.sync.aligned.m8n8.x4.shared.b16 {%0,%1,%2,%3}, [%4];"
                 : "=r"(r[0]), "=r"(r[1]), "=r"(r[2]), "=r"(r[3]) : "r"(a));
}
__device__ __forceinline__ void mma16816(float* c, const uint32_t* a, const uint32_t* b) {
    asm volatile("mma.sync.aligned.m16n8k16.row.col.f32.f16.f16.f32 "
                 "{%0,%1,%2,%3},{%4,%5,%6,%7},{%8,%9},{%0,%1,%2,%3};"
                 : "+f"(c[0]), "+f"(c[1]), "+f"(c[2]), "+f"(c[3])
                 : "r"(a[0]), "r"(a[1]), "r"(a[2]), "r"(a[3]), "r"(b[0]), "r"(b[1]));
}

// ---------------- pre-pass: x -> padded NHWC fp16 ----------------
__global__ __launch_bounds__(256) void prep_x(const float* __restrict__ x) {
    __shared__ float sx[CIN * 57];     // pitch 57: LDS conflicts 16-way -> 2-way
    const int yp = blockIdx.x;         // 0..57 padded row
    const int n  = blockIdx.y;
    const int tid = threadIdx.x;
    const bool rowvalid = (yp >= 1 && yp <= 56);
    if (rowvalid) {
        const int y = yp - 1;
#pragma unroll
        for (int it = 0; it < 7; it++) {              // 128c x 14 float4 = 1792
            int idx = tid + it * 256;
            int c = idx / 14, xi = idx - c * 14;
            float4 v = *(const float4*)(x + (((size_t)n * CIN + c) * 56 + y) * 56 + xi * 4);
            int b = c * 57 + xi * 4;
            sx[b] = v.x; sx[b + 1] = v.y; sx[b + 2] = v.z; sx[b + 3] = v.w;
        }
    }
    __syncthreads();
    for (int idx = tid; idx < 58 * 64; idx += 256) {
        int xp = idx >> 6, cp = (idx & 63) * 2;
        float v0 = 0.f, v1 = 0.f;
        if (rowvalid && xp >= 1 && xp <= 56) {
            v0 = sx[cp * 57 + (xp - 1)];
            v1 = sx[(cp + 1) * 57 + (xp - 1)];
        }
        *(__half2*)(g_xh + ((size_t)n * QP + yp * 58 + xp) * CIN + cp) =
            __floats2half2_rn(v0, v1);
    }
}

// ---------------- pre-pass: w -> [tap][oc][c] fp16 ----------------
__global__ __launch_bounds__(256) void prep_w(const float* __restrict__ w) {
    int idx = blockIdx.x * 256 + threadIdx.x;       // 9*256*64 half2 items
    if (idx < 9 * COUT * 64) {
        int tap = idx / (COUT * 64);
        int rem = idx - tap * (COUT * 64);
        int oc = rem >> 6, cp = (rem & 63) * 2;
        float v0 = w[((size_t)(oc * CIN + cp)) * 9 + tap];
        float v1 = w[((size_t)(oc * CIN + cp + 1)) * 9 + tap];
        *(__half2*)(g_wh + ((size_t)tap * COUT + oc) * CIN + cp) =
            __floats2half2_rn(v0, v1);
    }
}

// ---------------- main GEMM ----------------
__global__ __launch_bounds__(256, 1) void conv_mma(float* __restrict__ out) {
    extern __shared__ char smem[];
    const uint32_t sbA = smem_u32(smem);
    const uint32_t sbB = sbA + SMA;
    const int tid = threadIdx.x, lane = tid & 31, wid = tid >> 5;
    const int strip = blockIdx.x, ochalf = blockIdx.y, n_img = blockIdx.z;
    const int Q0 = strip * 256;
    const int oc0 = ochalf * 128;
    const int Mb  = (wid & 3) * 64;    // warp M base within strip
    const int NbL = (wid >> 2) * 64;   // warp N base within oc half

    float acc[4][8][4];
#pragma unroll
    for (int i = 0; i < 4; i++)
#pragma unroll
        for (int j = 0; j < 8; j++)
#pragma unroll
            for (int k = 0; k < 4; k++) acc[i][j][k] = 0.f;

    auto stageB = [&](int tap, int b) {
        const __half* src = g_wh + ((size_t)tap * COUT + oc0) * CIN;
        const uint32_t d0 = sbB + b * SMB;
        for (int idx = tid; idx < 2048; idx += 256) {
            int row = idx >> 4, t = idx & 15;
            cpa16(d0 + swz(row, t), src + (size_t)row * CIN + t * 8);
        }
    };

    // prologue: A strip (once) + B tap0 in group 0, B tap1 in group 1
    {
        const __half* src = g_xh + ((size_t)n_img * QP + Q0) * CIN;
        for (int idx = tid; idx < AROWS * 16; idx += 256) {
            int row = idx >> 4, t = idx & 15;
            cpa16(sbA + swz(row, t), src + (size_t)row * CIN + t * 8);
        }
    }
    stageB(0, 0);
    asm volatile("cp.async.commit_group;" ::: "memory");
    stageB(1, 1);
    asm volatile("cp.async.commit_group;" ::: "memory");

    for (int tap = 0; tap < 9; tap++) {
        if (tap < 8) asm volatile("cp.async.wait_group 1;" ::: "memory");
        else         asm volatile("cp.async.wait_group 0;" ::: "memory");
        __syncthreads();

        const int offq = (tap / 3) * 58 + (tap % 3);
        const uint32_t bbase = sbB + (tap & 1) * SMB;

#pragma unroll
        for (int ks = 0; ks < 8; ks++) {
            uint32_t af[4][4], bf[4][4];
            const int ta = ks * 2 + (lane >> 4);
            const int tb = ks * 2 + ((lane >> 3) & 1);
#pragma unroll
            for (int mt = 0; mt < 4; mt++) {
                int row = offq + Mb + mt * 16 + (lane & 15);
                ldsm4(af[mt], sbA + swz(row, ta));
            }
#pragma unroll
            for (int np = 0; np < 4; np++) {
                int row = NbL + np * 16 + (lane & 7) + ((lane >> 4) << 3);
                ldsm4(bf[np], bbase + swz(row, tb));
            }
#pragma unroll
            for (int mt = 0; mt < 4; mt++)
#pragma unroll
                for (int np = 0; np < 4; np++) {
                    mma16816(acc[mt][np * 2],     af[mt], bf[np]);
                    mma16816(acc[mt][np * 2 + 1], af[mt], bf[np] + 2);
                }
        }
        __syncthreads();
        if (tap + 2 < 9) {
            stageB(tap + 2, tap & 1);
            asm volatile("cp.async.commit_group;" ::: "memory");
        }
    }

    // ---- epilogue: registers -> NCHW out ----
#pragma unroll
    for (int mt = 0; mt < 4; mt++) {
        const int m0 = Mb + mt * 16 + (lane >> 2);
#pragma unroll
        for (int nt = 0; nt < 8; nt++) {
            const int n0 = oc0 + NbL + nt * 8 + (lane & 3) * 2;
            const size_t ob = ((size_t)n_img * COUT + n0) * 3136;
            int q = Q0 + m0;
            int y = q / 58, x = q - y * 58;
            if (y < 56 && x < 56) {
                size_t o = ob + y * 56 + x;
                out[o]        = acc[mt][nt][0];
                out[o + 3136] = acc[mt][nt][1];
            }
            q += 8;
            y = q / 58; x = q - y * 58;
            if (y < 56 && x < 56) {
                size_t o = ob + y * 56 + x;
                out[o]        = acc[mt][nt][2];
                out[o + 3136] = acc[mt][nt][3];
            }
        }
    }
}

// ---------------- launch ----------------
extern "C" void kernel_launch(void* const* d_in, const int* in_sizes, int n_in,
                              void* d_out, int out_size) {
    const float* x = (const float*)d_in[0];   // [32,128,56,56]
    const float* w = (const float*)d_in[1];   // [256,128,3,3]
    float* out = (float*)d_out;               // [32,256,56,56]

    static bool attr_set = false;
    if (!attr_set) {
        cudaFuncSetAttribute(conv_mma, cudaFuncAttributeMaxDynamicSharedMemorySize, SM_TOTAL);
        attr_set = true;
    }

    prep_x<<<dim3(58, NIMG), 256>>>(x);
    prep_w<<<(9 * COUT * 64 + 255) / 256, 256>>>(w);
    conv_mma<<<dim3(NSTRIP, 2, NIMG), 256, SM_TOTAL>>>(out);
}

// round 8
// speedup vs baseline: 16.5574x; 1.1342x over previous
#include <cuda_runtime.h>
#include <cuda_fp16.h>
#include <cstdint>

// Conv 3x3 s1 p1, NCHW fp32: x[32,128,56,56] * w[256,128,3,3] -> out[32,256,56,56]
// Implicit GEMM on mma.sync m16n8k16 fp16 (fp32 accum).
//   Per CTA (128 thr, 4 warps): M=128 pixel strip, N=64 oc, K=1152 (9 taps x 128c).
//   A: padded strip (256 rows x 256B) resident in smem, staged once.
//   B: 16KB per tap, 3-stage cp.async ring, ONE __syncthreads per tap.
//   smem 112KB -> 2 CTAs/SM: prologue/epilogue/barrier overlap across CTAs.
// Row-relative swizzle: 16B col t stored at (t ^ (row&7)) -> conflict-free ldmatrix.

#define QP     3520
#define CIN    128
#define COUT   256
#define NIMG   32
#define NSTRIP 26          // 26*128 = 3328 >= last valid q 3245
#define AROWS  256         // 128 + max tap offset 118, rounded up
#define SMA    (AROWS * 256)           // 64 KB
#define SMB    16384                   // 64 oc rows x 256B
#define SM_TOTAL (SMA + 3 * SMB)       // 114688 = 112 KB

// ---------------- device scratch (static = allowed) ----------------
__device__ __align__(256) __half g_xh[(size_t)NIMG * QP * CIN];
__device__ __align__(256) __half g_wh[9 * COUT * CIN];

// ---------------- helpers ----------------
__device__ __forceinline__ uint32_t smem_u32(const void* p) {
    uint32_t a;
    asm("{ .reg .u64 t; cvta.to.shared.u64 t, %1; cvt.u32.u64 %0, t; }" : "=r"(a) : "l"(p));
    return a;
}
__device__ __forceinline__ uint32_t swz(int row, int t) {
    return (uint32_t)(row * 256 + ((t ^ (row & 7)) << 4));
}
__device__ __forceinline__ void cpa16(uint32_t saddr, const void* gptr) {
    asm volatile("cp.async.cg.shared.global [%0], [%1], 16;"
                 :: "r"(saddr), "l"(__cvta_generic_to_global(gptr)) : "memory");
}
__device__ __forceinline__ void ldsm4(uint32_t* r, uint32_t a) {
    asm volatile("ldmatrix.sync.aligned.m8n8.x4.shared.b16 {%0,%1,%2,%3}, [%4];"
                 : "=r"(r[0]), "=r"(r[1]), "=r"(r[2]), "=r"(r[3]) : "r"(a));
}
__device__ __forceinline__ void mma16816(float* c, const uint32_t* a, const uint32_t* b) {
    asm volatile("mma.sync.aligned.m16n8k16.row.col.f32.f16.f16.f32 "
                 "{%0,%1,%2,%3},{%4,%5,%6,%7},{%8,%9},{%0,%1,%2,%3};"
                 : "+f"(c[0]), "+f"(c[1]), "+f"(c[2]), "+f"(c[3])
                 : "r"(a[0]), "r"(a[1]), "r"(a[2]), "r"(a[3]), "r"(b[0]), "r"(b[1]));
}

// ---------------- pre-pass: x -> padded NHWC fp16 ----------------
__global__ __launch_bounds__(256) void prep_x(const float* __restrict__ x) {
    __shared__ float sx[CIN * 57];     // pitch 57 -> mild LDS conflicts only
    const int yp = blockIdx.x;         // 0..57 padded row
    const int n  = blockIdx.y;
    const int tid = threadIdx.x;
    const bool rowvalid = (yp >= 1 && yp <= 56);
    if (rowvalid) {
        const int y = yp - 1;
#pragma unroll
        for (int it = 0; it < 7; it++) {              // 128c x 14 float4
            int idx = tid + it * 256;
            int c = idx / 14, xi = idx - c * 14;
            float4 v = *(const float4*)(x + (((size_t)n * CIN + c) * 56 + y) * 56 + xi * 4);
            int b = c * 57 + xi * 4;
            sx[b] = v.x; sx[b + 1] = v.y; sx[b + 2] = v.z; sx[b + 3] = v.w;
        }
    }
    __syncthreads();
    for (int idx = tid; idx < 58 * 64; idx += 256) {
        int xp = idx >> 6, cp = (idx & 63) * 2;
        float v0 = 0.f, v1 = 0.f;
        if (rowvalid && xp >= 1 && xp <= 56) {
            v0 = sx[cp * 57 + (xp - 1)];
            v1 = sx[(cp + 1) * 57 + (xp - 1)];
        }
        *(__half2*)(g_xh + ((size_t)n * QP + yp * 58 + xp) * CIN + cp) =
            __floats2half2_rn(v0, v1);
    }
}

// ---------------- pre-pass: w -> [tap][oc][c] fp16 ----------------
__global__ __launch_bounds__(256) void prep_w(const float* __restrict__ w) {
    int idx = blockIdx.x * 256 + threadIdx.x;       // 9*256*64 half2 items
    if (idx < 9 * COUT * 64) {
        int tap = idx / (COUT * 64);
        int rem = idx - tap * (COUT * 64);
        int oc = rem >> 6, cp = (rem & 63) * 2;
        float v0 = w[((size_t)(oc * CIN + cp)) * 9 + tap];
        float v1 = w[((size_t)(oc * CIN + cp + 1)) * 9 + tap];
        *(__half2*)(g_wh + ((size_t)tap * COUT + oc) * CIN + cp) =
            __floats2half2_rn(v0, v1);
    }
}

// ---------------- main GEMM ----------------
__global__ void __launch_bounds__(128, 2) conv_mma(float* __restrict__ out) {
    extern __shared__ char smem[];
    const uint32_t sbA = smem_u32(smem);
    const uint32_t sbB = sbA + SMA;
    const int tid = threadIdx.x, lane = tid & 31, wid = tid >> 5;
    const int strip = blockIdx.x, quad = blockIdx.y, n_img = blockIdx.z;
    const int Q0 = strip * 128;
    const int oc0 = quad * 64;
    const int Mb = (wid & 1) * 64;     // warp M base
    const int Nb = (wid >> 1) * 32;    // warp N base (within 64-oc tile)

    float acc[4][4][4];
#pragma unroll
    for (int i = 0; i < 4; i++)
#pragma unroll
        for (int j = 0; j < 4; j++)
#pragma unroll
            for (int k = 0; k < 4; k++) acc[i][j][k] = 0.f;

    auto stageB = [&](int tap, int b) {
        const __half* src = g_wh + ((size_t)tap * COUT + oc0) * CIN;
        const uint32_t d0 = sbB + b * SMB;
#pragma unroll
        for (int it = 0; it < 8; it++) {               // 64 rows x 16 cols / 128 thr
            int idx = tid + it * 128;
            int row = idx >> 4, t = idx & 15;
            cpa16(d0 + swz(row, t), src + (size_t)row * CIN + t * 8);
        }
        asm volatile("cp.async.commit_group;" ::: "memory");
    };

    // prologue: A strip (group 0), B tap0 (group 1), B tap1 (group 2)
    {
        const __half* src = g_xh + ((size_t)n_img * QP + Q0) * CIN;
#pragma unroll
        for (int it = 0; it < 32; it++) {              // 256 rows x 16 cols / 128 thr
            int idx = tid + it * 128;
            int row = idx >> 4, t = idx & 15;
            cpa16(sbA + swz(row, t), src + (size_t)row * CIN + t * 8);
        }
        asm volatile("cp.async.commit_group;" ::: "memory");
    }
    stageB(0, 0);
    stageB(1, 1);

    for (int tap = 0; tap < 9; tap++) {
        if (tap < 8) asm volatile("cp.async.wait_group 1;" ::: "memory");
        else         asm volatile("cp.async.wait_group 0;" ::: "memory");
        __syncthreads();
        // stage AFTER the sync: buffer (tap+2)%3 was last read at iter tap-1,
        // and every warp passed this sync only after finishing that compute.
        if (tap + 2 < 9) stageB(tap + 2, (tap + 2) % 3);

        const int offq = (tap / 3) * 58 + (tap % 3);
        const uint32_t bbase = sbB + (tap % 3) * SMB;

#pragma unroll
        for (int ks = 0; ks < 8; ks++) {
            uint32_t af[4][4], bf[2][4];
            const int ta = ks * 2 + (lane >> 4);
            const int tb = ks * 2 + ((lane >> 3) & 1);
#pragma unroll
            for (int mt = 0; mt < 4; mt++) {
                int row = offq + Mb + mt * 16 + (lane & 15);
                ldsm4(af[mt], sbA + swz(row, ta));
            }
#pragma unroll
            for (int np = 0; np < 2; np++) {
                int row = Nb + np * 16 + (lane & 7) + ((lane >> 4) << 3);
                ldsm4(bf[np], bbase + swz(row, tb));
            }
#pragma unroll
            for (int mt = 0; mt < 4; mt++)
#pragma unroll
                for (int np = 0; np < 2; np++) {
                    mma16816(acc[mt][np * 2],     af[mt], bf[np]);
                    mma16816(acc[mt][np * 2 + 1], af[mt], bf[np] + 2);
                }
        }
    }

    // ---- epilogue: registers -> NCHW out ----
#pragma unroll
    for (int mt = 0; mt < 4; mt++) {
        const int m0 = Mb + mt * 16 + (lane >> 2);
#pragma unroll
        for (int nt = 0; nt < 4; nt++) {
            const int n0 = oc0 + Nb + nt * 8 + (lane & 3) * 2;
            const size_t ob = ((size_t)n_img * COUT + n0) * 3136;
            int q = Q0 + m0;
            int y = q / 58, x = q - y * 58;
            if (y < 56 && x < 56) {
                size_t o = ob + y * 56 + x;
                out[o]        = acc[mt][nt][0];
                out[o + 3136] = acc[mt][nt][1];
            }
            q += 8;
            y = q / 58; x = q - y * 58;
            if (y < 56 && x < 56) {
                size_t o = ob + y * 56 + x;
                out[o]        = acc[mt][nt][2];
                out[o + 3136] = acc[mt][nt][3];
            }
        }
    }
}

// ---------------- launch ----------------
extern "C" void kernel_launch(void* const* d_in, const int* in_sizes, int n_in,
                              void* d_out, int out_size) {
    const float* x = (const float*)d_in[0];   // [32,128,56,56]
    const float* w = (const float*)d_in[1];   // [256,128,3,3]
    float* out = (float*)d_out;               // [32,256,56,56]

    static bool attr_set = false;
    if (!attr_set) {
        cudaFuncSetAttribute(conv_mma, cudaFuncAttributeMaxDynamicSharedMemorySize, SM_TOTAL);
        attr_set = true;
    }

    prep_x<<<dim3(58, NIMG), 256>>>(x);
    prep_w<<<(9 * COUT * 64 + 255) / 256, 256>>>(w);
    conv_mma<<<dim3(NSTRIP, 4, NIMG), 128, SM_TOTAL>>>(out);
}

// round 9
// speedup vs baseline: 16.6192x; 1.0037x over previous
#include <cuda_runtime.h>
#include <cuda_fp16.h>
#include <cstdint>

// Conv 3x3 s1 p1, NCHW fp32: x[32,128,56,56] * w[256,128,3,3] -> out[32,256,56,56]
// Implicit GEMM on mma.sync m16n8k16 fp16 (fp32 accum).
//   Per CTA (128 thr, 4 warps of 64x64): M=128 strip, N=128 oc, K=1152.
//   K order: c-half-major (9 taps on c[0:64], then 9 taps on c[64:128]).
//   A: strip as 128B rows (64 c), one 32KB buffer per c-half; half1 prefetched.
//   B: 16KB per (tap,chalf) chunk, 3-stage cp.async ring, one sync per chunk.
//   smem 112KB -> 2 CTAs/SM. wf/HMMA = 1.0 (was 1.5) -> L1 & HMMA both ~100%.

#define QP     3520
#define CIN    128
#define COUT   256
#define NIMG   32
#define NSTRIP 26          // 26*128 = 3328 >= last valid q 3245
#define AROWS  256         // 128 + max tap offset 118, rounded up
#define SMA_H  (AROWS * 128)           // 32 KB per c-half
#define SMB    16384                   // 128 oc rows x 128B
#define SM_TOTAL (2 * SMA_H + 3 * SMB) // 114688 = 112 KB

// ---------------- device scratch (static = allowed) ----------------
__device__ __align__(256) __half g_xh[(size_t)NIMG * QP * CIN];
__device__ __align__(256) __half g_wh[9 * COUT * CIN];

// ---------------- helpers ----------------
__device__ __forceinline__ uint32_t smem_u32(const void* p) {
    uint32_t a;
    asm("{ .reg .u64 t; cvta.to.shared.u64 t, %1; cvt.u32.u64 %0, t; }" : "=r"(a) : "l"(p));
    return a;
}
// 128B-pitch rows, classic swizzle: 16B col t stored at t ^ (row&7)
__device__ __forceinline__ uint32_t swz(int row, int t) {
    return (uint32_t)(row * 128 + ((t ^ (row & 7)) << 4));
}
__device__ __forceinline__ void cpa16(uint32_t saddr, const void* gptr) {
    asm volatile("cp.async.cg.shared.global [%0], [%1], 16;"
                 :: "r"(saddr), "l"(__cvta_generic_to_global(gptr)) : "memory");
}
__device__ __forceinline__ void ldsm4(uint32_t* r, uint32_t a) {
    asm volatile("ldmatrix.sync.aligned.m8n8.x4.shared.b16 {%0,%1,%2,%3}, [%4];"
                 : "=r"(r[0]), "=r"(r[1]), "=r"(r[2]), "=r"(r[3]) : "r"(a));
}
__device__ __forceinline__ void mma16816(float* c, const uint32_t* a, const uint32_t* b) {
    asm volatile("mma.sync.aligned.m16n8k16.row.col.f32.f16.f16.f32 "
                 "{%0,%1,%2,%3},{%4,%5,%6,%7},{%8,%9},{%0,%1,%2,%3};"
                 : "+f"(c[0]), "+f"(c[1]), "+f"(c[2]), "+f"(c[3])
                 : "r"(a[0]), "r"(a[1]), "r"(a[2]), "r"(a[3]), "r"(b[0]), "r"(b[1]));
}

// ---------------- pre-pass: x -> padded NHWC fp16 ----------------
__global__ __launch_bounds__(256) void prep_x(const float* __restrict__ x) {
    __shared__ float sx[CIN * 57];
    const int yp = blockIdx.x;         // 0..57 padded row
    const int n  = blockIdx.y;
    const int tid = threadIdx.x;
    const bool rowvalid = (yp >= 1 && yp <= 56);
    if (rowvalid) {
        const int y = yp - 1;
#pragma unroll
        for (int it = 0; it < 7; it++) {              // 128c x 14 float4
            int idx = tid + it * 256;
            int c = idx / 14, xi = idx - c * 14;
            float4 v = *(const float4*)(x + (((size_t)n * CIN + c) * 56 + y) * 56 + xi * 4);
            int b = c * 57 + xi * 4;
            sx[b] = v.x; sx[b + 1] = v.y; sx[b + 2] = v.z; sx[b + 3] = v.w;
        }
    }
    __syncthreads();
    for (int idx = tid; idx < 58 * 64; idx += 256) {
        int xp = idx >> 6, cp = (idx & 63) * 2;
        float v0 = 0.f, v1 = 0.f;
        if (rowvalid && xp >= 1 && xp <= 56) {
            v0 = sx[cp * 57 + (xp - 1)];
            v1 = sx[(cp + 1) * 57 + (xp - 1)];
        }
        *(__half2*)(g_xh + ((size_t)n * QP + yp * 58 + xp) * CIN + cp) =
            __floats2half2_rn(v0, v1);
    }
}

// ---------------- pre-pass: w -> [tap][oc][c] fp16 ----------------
__global__ __launch_bounds__(256) void prep_w(const float* __restrict__ w) {
    int idx = blockIdx.x * 256 + threadIdx.x;       // 9*256*64 half2 items
    if (idx < 9 * COUT * 64) {
        int tap = idx / (COUT * 64);
        int rem = idx - tap * (COUT * 64);
        int oc = rem >> 6, cp = (rem & 63) * 2;
        float v0 = w[((size_t)(oc * CIN + cp)) * 9 + tap];
        float v1 = w[((size_t)(oc * CIN + cp + 1)) * 9 + tap];
        *(__half2*)(g_wh + ((size_t)tap * COUT + oc) * CIN + cp) =
            __floats2half2_rn(v0, v1);
    }
}

// ---------------- main GEMM ----------------
__global__ void __launch_bounds__(128, 2) conv_mma(float* __restrict__ out) {
    extern __shared__ char smem[];
    const uint32_t sbA = smem_u32(smem);                 // 2 x 32KB (c-halves)
    const uint32_t sbB = sbA + 2 * SMA_H;                // 3 x 16KB ring
    const int tid = threadIdx.x, lane = tid & 31, wid = tid >> 5;
    const int strip = blockIdx.x, ochalf = blockIdx.y, n_img = blockIdx.z;
    const int Q0 = strip * 128;
    const int oc0 = ochalf * 128;
    const int Mb = (wid & 1) * 64;     // warp M base
    const int Nb = (wid >> 1) * 64;    // warp N base

    float acc[4][8][4];
#pragma unroll
    for (int i = 0; i < 4; i++)
#pragma unroll
        for (int j = 0; j < 8; j++)
#pragma unroll
            for (int k = 0; k < 4; k++) acc[i][j][k] = 0.f;

    // stage A c-half: 256 rows x 8x16B = 2048 cp (16/thread)
    auto stageA = [&](int half) {
        const __half* src = g_xh + ((size_t)n_img * QP + Q0) * CIN + half * 64;
        const uint32_t d0 = sbA + half * SMA_H;
#pragma unroll
        for (int it = 0; it < 16; it++) {
            int idx = tid + it * 128;
            int row = idx >> 3, t = idx & 7;
            cpa16(d0 + swz(row, t), src + (size_t)row * CIN + t * 8);
        }
    };
    // stage B chunk: 128 oc rows x 8x16B = 1024 cp (8/thread)
    auto stageB = [&](int chunk, int b) {
        const int tap = (chunk < 9) ? chunk : chunk - 9;
        const int half = (chunk < 9) ? 0 : 1;
        const __half* src = g_wh + ((size_t)tap * COUT + oc0) * CIN + half * 64;
        const uint32_t d0 = sbB + b * SMB;
#pragma unroll
        for (int it = 0; it < 8; it++) {
            int idx = tid + it * 128;
            int row = idx >> 3, t = idx & 7;
            cpa16(d0 + swz(row, t), src + (size_t)row * CIN + t * 8);
        }
    };

    // prologue: G0 = {A half0, B0}, G1 = {B1}
    stageA(0);
    stageB(0, 0);
    asm volatile("cp.async.commit_group;" ::: "memory");
    stageB(1, 1);
    asm volatile("cp.async.commit_group;" ::: "memory");

    for (int ch = 0; ch < 18; ch++) {
        if (ch < 17) asm volatile("cp.async.wait_group 1;" ::: "memory");
        else         asm volatile("cp.async.wait_group 0;" ::: "memory");
        __syncthreads();
        // stage after sync: ring slot (ch+2)%3 was last read at iter ch-1
        if (ch + 2 < 18) {
            stageB(ch + 2, (ch + 2) % 3);
            if (ch == 0) stageA(1);   // A half1 prefetch, same group; needed at ch=9
            asm volatile("cp.async.commit_group;" ::: "memory");
        }

        const int tap = (ch < 9) ? ch : ch - 9;
        const int offq = (tap / 3) * 58 + (tap % 3);
        const uint32_t abase = sbA + ((ch < 9) ? 0 : SMA_H);
        const uint32_t bbase = sbB + (ch % 3) * SMB;

#pragma unroll
        for (int ks = 0; ks < 4; ks++) {
            uint32_t af[4][4], bf[4][4];
            const int ta = ks * 2 + (lane >> 4);
            const int tb = ks * 2 + ((lane >> 3) & 1);
#pragma unroll
            for (int mt = 0; mt < 4; mt++) {
                int row = offq + Mb + mt * 16 + (lane & 15);
                ldsm4(af[mt], abase + swz(row, ta));
            }
#pragma unroll
            for (int np = 0; np < 4; np++) {
                int row = Nb + np * 16 + (lane & 7) + ((lane >> 4) << 3);
                ldsm4(bf[np], bbase + swz(row, tb));
            }
#pragma unroll
            for (int mt = 0; mt < 4; mt++)
#pragma unroll
                for (int np = 0; np < 4; np++) {
                    mma16816(acc[mt][np * 2],     af[mt], bf[np]);
                    mma16816(acc[mt][np * 2 + 1], af[mt], bf[np] + 2);
                }
        }
    }

    // ---- epilogue: registers -> NCHW out ----
#pragma unroll
    for (int mt = 0; mt < 4; mt++) {
        const int m0 = Mb + mt * 16 + (lane >> 2);
#pragma unroll
        for (int nt = 0; nt < 8; nt++) {
            const int n0 = oc0 + Nb + nt * 8 + (lane & 3) * 2;
            const size_t ob = ((size_t)n_img * COUT + n0) * 3136;
            int q = Q0 + m0;
            int y = q / 58, x = q - y * 58;
            if (y < 56 && x < 56) {
                size_t o = ob + y * 56 + x;
                out[o]        = acc[mt][nt][0];
                out[o + 3136] = acc[mt][nt][1];
            }
            q += 8;
            y = q / 58; x = q - y * 58;
            if (y < 56 && x < 56) {
                size_t o = ob + y * 56 + x;
                out[o]        = acc[mt][nt][2];
                out[o + 3136] = acc[mt][nt][3];
            }
        }
    }
}

// ---------------- launch ----------------
extern "C" void kernel_launch(void* const* d_in, const int* in_sizes, int n_in,
                              void* d_out, int out_size) {
    const float* x = (const float*)d_in[0];   // [32,128,56,56]
    const float* w = (const float*)d_in[1];   // [256,128,3,3]
    float* out = (float*)d_out;               // [32,256,56,56]

    static bool attr_set = false;
    if (!attr_set) {
        cudaFuncSetAttribute(conv_mma, cudaFuncAttributeMaxDynamicSharedMemorySize, SM_TOTAL);
        attr_set = true;
    }

    prep_x<<<dim3(58, NIMG), 256>>>(x);
    prep_w<<<(9 * COUT * 64 + 255) / 256, 256>>>(w);
    conv_mma<<<dim3(NSTRIP, 2, NIMG), 128, SM_TOTAL>>>(out);
}

// round 10
// speedup vs baseline: 16.7064x; 1.0052x over previous
#include <cuda_runtime.h>
#include <cuda_fp16.h>
#include <cstdint>

// Conv 3x3 s1 p1, NCHW fp32: x[32,128,56,56] * w[256,128,3,3] -> out[32,256,56,56]
// Implicit GEMM on mma.sync m16n8k16 fp16 (fp32 accum).
//   Per CTA (128 thr, 4 warps of 64x64): M=128 strip, N=128 oc, K=1152.
//   K order: c-half-major (9 taps on c[0:64], then 9 taps on c[64:128]).
//   A: strip as 128B rows (64 c), one 32KB buffer per c-half; half1 prefetched.
//   B: 16KB per (tap,chalf) chunk, 3-stage cp.async ring, one sync per chunk.
//   smem 112KB -> 2 CTAs/SM.
// R10: prep_x v3 (16B vectorized stores) — conv_mma unchanged from R9.

#define QP     3520
#define CIN    128
#define COUT   256
#define NIMG   32
#define NSTRIP 26          // 26*128 = 3328 >= last valid q 3245
#define AROWS  256         // 128 + max tap offset 118, rounded up
#define SMA_H  (AROWS * 128)           // 32 KB per c-half
#define SMB    16384                   // 128 oc rows x 128B
#define SM_TOTAL (2 * SMA_H + 3 * SMB) // 114688 = 112 KB

// ---------------- device scratch (static = allowed) ----------------
__device__ __align__(256) __half g_xh[(size_t)NIMG * QP * CIN];
__device__ __align__(256) __half g_wh[9 * COUT * CIN];

// ---------------- helpers ----------------
__device__ __forceinline__ uint32_t smem_u32(const void* p) {
    uint32_t a;
    asm("{ .reg .u64 t; cvta.to.shared.u64 t, %1; cvt.u32.u64 %0, t; }" : "=r"(a) : "l"(p));
    return a;
}
// 128B-pitch rows, classic swizzle: 16B col t stored at t ^ (row&7)
__device__ __forceinline__ uint32_t swz(int row, int t) {
    return (uint32_t)(row * 128 + ((t ^ (row & 7)) << 4));
}
__device__ __forceinline__ void cpa16(uint32_t saddr, const void* gptr) {
    asm volatile("cp.async.cg.shared.global [%0], [%1], 16;"
                 :: "r"(saddr), "l"(__cvta_generic_to_global(gptr)) : "memory");
}
__device__ __forceinline__ void ldsm4(uint32_t* r, uint32_t a) {
    asm volatile("ldmatrix.sync.aligned.m8n8.x4.shared.b16 {%0,%1,%2,%3}, [%4];"
                 : "=r"(r[0]), "=r"(r[1]), "=r"(r[2]), "=r"(r[3]) : "r"(a));
}
__device__ __forceinline__ void mma16816(float* c, const uint32_t* a, const uint32_t* b) {
    asm volatile("mma.sync.aligned.m16n8k16.row.col.f32.f16.f16.f32 "
                 "{%0,%1,%2,%3},{%4,%5,%6,%7},{%8,%9},{%0,%1,%2,%3};"
                 : "+f"(c[0]), "+f"(c[1]), "+f"(c[2]), "+f"(c[3])
                 : "r"(a[0]), "r"(a[1]), "r"(a[2]), "r"(a[3]), "r"(b[0]), "r"(b[1]));
}

// ---------------- pre-pass: x -> padded NHWC fp16 (v3: 16B stores) ----------------
__global__ __launch_bounds__(256) void prep_x(const float* __restrict__ x) {
    __shared__ float sx[CIN * 57];     // pitch 57
    const int yp = blockIdx.x;         // 0..57 padded row
    const int n  = blockIdx.y;
    const int tid = threadIdx.x;
    const bool rowvalid = (yp >= 1 && yp <= 56);
    if (rowvalid) {
        const int y = yp - 1;
#pragma unroll
        for (int it = 0; it < 7; it++) {              // 128c x 14 float4
            int idx = tid + it * 256;
            int c = idx / 14, xi = idx - c * 14;
            float4 v = *(const float4*)(x + (((size_t)n * CIN + c) * 56 + y) * 56 + xi * 4);
            int b = c * 57 + xi * 4;
            sx[b] = v.x; sx[b + 1] = v.y; sx[b + 2] = v.z; sx[b + 3] = v.w;
        }
    }
    __syncthreads();
    // store: one STG.128 (8 channels) per item; 58*16 items
    const size_t rowbase = ((size_t)n * QP + (size_t)yp * 58) * CIN;
#pragma unroll 2
    for (int idx = tid; idx < 58 * 16; idx += 256) {
        int xp = idx >> 4, cg = (idx & 15) * 8;
        uint4 pack;
        if (rowvalid && xp >= 1 && xp <= 56) {
            const float* s = sx + cg * 57 + (xp - 1);
            __half2 h0 = __floats2half2_rn(s[0],       s[57]);
            __half2 h1 = __floats2half2_rn(s[2 * 57],  s[3 * 57]);
            __half2 h2 = __floats2half2_rn(s[4 * 57],  s[5 * 57]);
            __half2 h3 = __floats2half2_rn(s[6 * 57],  s[7 * 57]);
            pack.x = *(uint32_t*)&h0; pack.y = *(uint32_t*)&h1;
            pack.z = *(uint32_t*)&h2; pack.w = *(uint32_t*)&h3;
        } else {
            pack = make_uint4(0, 0, 0, 0);
        }
        *(uint4*)(g_xh + rowbase + (size_t)xp * CIN + cg) = pack;
    }
}

// ---------------- pre-pass: w -> [tap][oc][c] fp16 ----------------
__global__ __launch_bounds__(256) void prep_w(const float* __restrict__ w) {
    int idx = blockIdx.x * 256 + threadIdx.x;       // 9*256*64 half2 items
    if (idx < 9 * COUT * 64) {
        int tap = idx / (COUT * 64);
        int rem = idx - tap * (COUT * 64);
        int oc = rem >> 6, cp = (rem & 63) * 2;
        float v0 = w[((size_t)(oc * CIN + cp)) * 9 + tap];
        float v1 = w[((size_t)(oc * CIN + cp + 1)) * 9 + tap];
        *(__half2*)(g_wh + ((size_t)tap * COUT + oc) * CIN + cp) =
            __floats2half2_rn(v0, v1);
    }
}

// ---------------- main GEMM (unchanged from R9) ----------------
__global__ void __launch_bounds__(128, 2) conv_mma(float* __restrict__ out) {
    extern __shared__ char smem[];
    const uint32_t sbA = smem_u32(smem);                 // 2 x 32KB (c-halves)
    const uint32_t sbB = sbA + 2 * SMA_H;                // 3 x 16KB ring
    const int tid = threadIdx.x, lane = tid & 31, wid = tid >> 5;
    const int strip = blockIdx.x, ochalf = blockIdx.y, n_img = blockIdx.z;
    const int Q0 = strip * 128;
    const int oc0 = ochalf * 128;
    const int Mb = (wid & 1) * 64;     // warp M base
    const int Nb = (wid >> 1) * 64;    // warp N base

    float acc[4][8][4];
#pragma unroll
    for (int i = 0; i < 4; i++)
#pragma unroll
        for (int j = 0; j < 8; j++)
#pragma unroll
            for (int k = 0; k < 4; k++) acc[i][j][k] = 0.f;

    auto stageA = [&](int half) {
        const __half* src = g_xh + ((size_t)n_img * QP + Q0) * CIN + half * 64;
        const uint32_t d0 = sbA + half * SMA_H;
#pragma unroll
        for (int it = 0; it < 16; it++) {
            int idx = tid + it * 128;
            int row = idx >> 3, t = idx & 7;
            cpa16(d0 + swz(row, t), src + (size_t)row * CIN + t * 8);
        }
    };
    auto stageB = [&](int chunk, int b) {
        const int tap = (chunk < 9) ? chunk : chunk - 9;
        const int half = (chunk < 9) ? 0 : 1;
        const __half* src = g_wh + ((size_t)tap * COUT + oc0) * CIN + half * 64;
        const uint32_t d0 = sbB + b * SMB;
#pragma unroll
        for (int it = 0; it < 8; it++) {
            int idx = tid + it * 128;
            int row = idx >> 3, t = idx & 7;
            cpa16(d0 + swz(row, t), src + (size_t)row * CIN + t * 8);
        }
    };

    // prologue: G0 = {A half0, B0}, G1 = {B1}
    stageA(0);
    stageB(0, 0);
    asm volatile("cp.async.commit_group;" ::: "memory");
    stageB(1, 1);
    asm volatile("cp.async.commit_group;" ::: "memory");

    for (int ch = 0; ch < 18; ch++) {
        if (ch < 17) asm volatile("cp.async.wait_group 1;" ::: "memory");
        else         asm volatile("cp.async.wait_group 0;" ::: "memory");
        __syncthreads();
        if (ch + 2 < 18) {
            stageB(ch + 2, (ch + 2) % 3);
            if (ch == 0) stageA(1);   // A half1 prefetch; needed at ch=9
            asm volatile("cp.async.commit_group;" ::: "memory");
        }

        const int tap = (ch < 9) ? ch : ch - 9;
        const int offq = (tap / 3) * 58 + (tap % 3);
        const uint32_t abase = sbA + ((ch < 9) ? 0 : SMA_H);
        const uint32_t bbase = sbB + (ch % 3) * SMB;

#pragma unroll
        for (int ks = 0; ks < 4; ks++) {
            uint32_t af[4][4], bf[4][4];
            const int ta = ks * 2 + (lane >> 4);
            const int tb = ks * 2 + ((lane >> 3) & 1);
#pragma unroll
            for (int mt = 0; mt < 4; mt++) {
                int row = offq + Mb + mt * 16 + (lane & 15);
                ldsm4(af[mt], abase + swz(row, ta));
            }
#pragma unroll
            for (int np = 0; np < 4; np++) {
                int row = Nb + np * 16 + (lane & 7) + ((lane >> 4) << 3);
                ldsm4(bf[np], bbase + swz(row, tb));
            }
#pragma unroll
            for (int mt = 0; mt < 4; mt++)
#pragma unroll
                for (int np = 0; np < 4; np++) {
                    mma16816(acc[mt][np * 2],     af[mt], bf[np]);
                    mma16816(acc[mt][np * 2 + 1], af[mt], bf[np] + 2);
                }
        }
    }

    // ---- epilogue: registers -> NCHW out ----
#pragma unroll
    for (int mt = 0; mt < 4; mt++) {
        const int m0 = Mb + mt * 16 + (lane >> 2);
#pragma unroll
        for (int nt = 0; nt < 8; nt++) {
            const int n0 = oc0 + Nb + nt * 8 + (lane & 3) * 2;
            const size_t ob = ((size_t)n_img * COUT + n0) * 3136;
            int q = Q0 + m0;
            int y = q / 58, x = q - y * 58;
            if (y < 56 && x < 56) {
                size_t o = ob + y * 56 + x;
                out[o]        = acc[mt][nt][0];
                out[o + 3136] = acc[mt][nt][1];
            }
            q += 8;
            y = q / 58; x = q - y * 58;
            if (y < 56 && x < 56) {
                size_t o = ob + y * 56 + x;
                out[o]        = acc[mt][nt][2];
                out[o + 3136] = acc[mt][nt][3];
            }
        }
    }
}

// ---------------- launch ----------------
extern "C" void kernel_launch(void* const* d_in, const int* in_sizes, int n_in,
                              void* d_out, int out_size) {
    const float* x = (const float*)d_in[0];   // [32,128,56,56]
    const float* w = (const float*)d_in[1];   // [256,128,3,3]
    float* out = (float*)d_out;               // [32,256,56,56]

    static bool attr_set = false;
    if (!attr_set) {
        cudaFuncSetAttribute(conv_mma, cudaFuncAttributeMaxDynamicSharedMemorySize, SM_TOTAL);
        attr_set = true;
    }

    prep_w<<<(9 * COUT * 64 + 255) / 256, 256>>>(w);
    prep_x<<<dim3(58, NIMG), 256>>>(x);
    conv_mma<<<dim3(NSTRIP, 2, NIMG), 128, SM_TOTAL>>>(out);
}

// round 14
// speedup vs baseline: 16.7284x; 1.0013x over previous
#include <cuda_runtime.h>
#include <cuda_fp16.h>
#include <cstdint>

// Conv 3x3 s1 p1, NCHW fp32: x[32,128,56,56] * w[256,128,3,3] -> out[32,256,56,56]
// Implicit GEMM on mma.sync m16n8k16 fp16 (fp32 accum).
//   Per CTA (128 thr, 4 warps of 64x64): M=128 strip, N=128 oc, K=1152.
//   K order: c-half-major (9 taps on c[0:64], then 9 taps on c[64:128]).
//   A: strip as 128B rows (64 c), one 32KB buffer per c-half; half1 prefetched.
//   B: 16KB per (tap,chalf) chunk, 3-stage cp.async ring, one sync per chunk.
//   smem 112KB -> 2 CTAs/SM.
// R14 = R13 with the misalignment fixed: sh16 pitch 130 -> 136 halves (272B,
//   16B-aligned; bank analysis at 68 words/row stays conflict-free).
//   conv_mma unchanged from the 170.7us R10 baseline.

#define QP     3520
#define CIN    128
#define COUT   256
#define NIMG   32
#define NSTRIP 26          // 26*128 = 3328 >= last valid q 3245
#define AROWS  256         // 128 + max tap offset 118, rounded up
#define SMA_H  (AROWS * 128)           // 32 KB per c-half
#define SMB    16384                   // 128 oc rows x 128B
#define SM_TOTAL (2 * SMA_H + 3 * SMB) // 114688 = 112 KB

// ---------------- device scratch (static = allowed) ----------------
__device__ __align__(256) __half g_xh[(size_t)NIMG * QP * CIN];
__device__ __align__(256) __half g_wh[9 * COUT * CIN];

// ---------------- helpers ----------------
__device__ __forceinline__ uint32_t smem_u32(const void* p) {
    uint32_t a;
    asm("{ .reg .u64 t; cvta.to.shared.u64 t, %1; cvt.u32.u64 %0, t; }" : "=r"(a) : "l"(p));
    return a;
}
// 128B-pitch rows, classic swizzle: 16B col t stored at t ^ (row&7)
__device__ __forceinline__ uint32_t swz(int row, int t) {
    return (uint32_t)(row * 128 + ((t ^ (row & 7)) << 4));
}
__device__ __forceinline__ void cpa16(uint32_t saddr, const void* gptr) {
    asm volatile("cp.async.cg.shared.global [%0], [%1], 16;"
                 :: "r"(saddr), "l"(__cvta_generic_to_global(gptr)) : "memory");
}
__device__ __forceinline__ void ldsm4(uint32_t* r, uint32_t a) {
    asm volatile("ldmatrix.sync.aligned.m8n8.x4.shared.b16 {%0,%1,%2,%3}, [%4];"
                 : "=r"(r[0]), "=r"(r[1]), "=r"(r[2]), "=r"(r[3]) : "r"(a));
}
__device__ __forceinline__ void mma16816(float* c, const uint32_t* a, const uint32_t* b) {
    asm volatile("mma.sync.aligned.m16n8k16.row.col.f32.f16.f16.f32 "
                 "{%0,%1,%2,%3},{%4,%5,%6,%7},{%8,%9},{%0,%1,%2,%3};"
                 : "+f"(c[0]), "+f"(c[1]), "+f"(c[2]), "+f"(c[3])
                 : "r"(a[0]), "r"(a[1]), "r"(a[2]), "r"(a[3]), "r"(b[0]), "r"(b[1]));
}

// ---------------- pre-pass: x -> padded NHWC fp16 (v4b, conflict-free + aligned) ----
// Phase A: NCHW row -> sx[c][x] fp32 (pitch 57).
// Phase B: transpose+convert -> sh16[xp][c] fp16, pitch 136 halfs (272B = 68 words,
//          16B-aligned rows; 68 mod 32 = 4 -> each 8-lane phase covers all 32 banks
//          for both STS.128 (xp-fastest) and LDS.128 (linear)).
// Phase C: linear copy sh16 -> g_xh, coalesced STG.128.
#define SXP 57
#define SHP 136
__global__ __launch_bounds__(256) void prep_x(const float* __restrict__ x) {
    __shared__ float  sx[CIN * SXP];
    __shared__ __align__(16) __half sh16[58 * SHP];
    const int yp = blockIdx.x;         // 0..57 padded row
    const int n  = blockIdx.y;
    const int tid = threadIdx.x;
    const bool rowvalid = (yp >= 1 && yp <= 56);

    if (rowvalid) {
        const int y = yp - 1;
#pragma unroll
        for (int it = 0; it < 7; it++) {              // 128c x 14 float4
            int idx = tid + it * 256;
            int c = idx / 14, xi = idx - c * 14;
            float4 v = *(const float4*)(x + (((size_t)n * CIN + c) * 56 + y) * 56 + xi * 4);
            int b = c * SXP + xi * 4;
            sx[b] = v.x; sx[b + 1] = v.y; sx[b + 2] = v.z; sx[b + 3] = v.w;
        }
    }
    __syncthreads();

    // Phase B: 58 xp x 16 channel-groups; xp fastest across lanes
#pragma unroll
    for (int it = 0; it < 4; it++) {
        int idx = tid + it * 256;                    // 0..1023, use < 928
        if (idx < 58 * 16) {
            int g  = idx / 58;                       // channel group (8 c)
            int xp = idx - g * 58;
            int cg = g * 8;
            uint4 pack = make_uint4(0, 0, 0, 0);
            if (rowvalid && xp >= 1 && xp <= 56) {
                const float* s = sx + cg * SXP + (xp - 1);
                __half2 h0 = __floats2half2_rn(s[0],       s[SXP]);
                __half2 h1 = __floats2half2_rn(s[2 * SXP], s[3 * SXP]);
                __half2 h2 = __floats2half2_rn(s[4 * SXP], s[5 * SXP]);
                __half2 h3 = __floats2half2_rn(s[6 * SXP], s[7 * SXP]);
                pack.x = *(uint32_t*)&h0; pack.y = *(uint32_t*)&h1;
                pack.z = *(uint32_t*)&h2; pack.w = *(uint32_t*)&h3;
            }
            *(uint4*)(sh16 + xp * SHP + cg) = pack;
        }
    }
    __syncthreads();

    // Phase C: coalesced store, 928 x 16B
    const size_t rowbase = ((size_t)n * QP + (size_t)yp * 58) * CIN;
#pragma unroll
    for (int it = 0; it < 4; it++) {
        int idx = tid + it * 256;
        if (idx < 58 * 16) {
            int xp = idx >> 4, k = idx & 15;
            uint4 v = *(const uint4*)(sh16 + xp * SHP + k * 8);
            *(uint4*)(g_xh + rowbase + (size_t)xp * CIN + k * 8) = v;
        }
    }
}

// ---------------- pre-pass: w -> [tap][oc][c] fp16 (v2, coalesced) ----------------
// One block per oc: contiguous 1152-float read, then 9 x 256B segment writes.
__global__ __launch_bounds__(128) void prep_w(const float* __restrict__ w) {
    __shared__ float sw[CIN * 9];      // this oc's weights, [c][tap]
    const int oc = blockIdx.x;
    const int tid = threadIdx.x;
    const float* src = w + (size_t)oc * CIN * 9;
#pragma unroll
    for (int it = 0; it < 9; it++) {   // 1152 floats / 128 thr
        int idx = tid + it * 128;
        sw[idx] = src[idx];
    }
    __syncthreads();
    // 9 taps x 16 chunks of 8 c = 144 items
    for (int idx = tid; idx < 9 * 16; idx += 128) {
        int tap = idx / 16, k = idx - tap * 16;
        int c0 = k * 8;
        __half2 h0 = __floats2half2_rn(sw[(c0    ) * 9 + tap], sw[(c0 + 1) * 9 + tap]);
        __half2 h1 = __floats2half2_rn(sw[(c0 + 2) * 9 + tap], sw[(c0 + 3) * 9 + tap]);
        __half2 h2 = __floats2half2_rn(sw[(c0 + 4) * 9 + tap], sw[(c0 + 5) * 9 + tap]);
        __half2 h3 = __floats2half2_rn(sw[(c0 + 6) * 9 + tap], sw[(c0 + 7) * 9 + tap]);
        uint4 pack;
        pack.x = *(uint32_t*)&h0; pack.y = *(uint32_t*)&h1;
        pack.z = *(uint32_t*)&h2; pack.w = *(uint32_t*)&h3;
        *(uint4*)(g_wh + ((size_t)tap * COUT + oc) * CIN + c0) = pack;
    }
}

// ---------------- main GEMM (unchanged from R10) ----------------
__global__ void __launch_bounds__(128, 2) conv_mma(float* __restrict__ out) {
    extern __shared__ char smem[];
    const uint32_t sbA = smem_u32(smem);                 // 2 x 32KB (c-halves)
    const uint32_t sbB = sbA + 2 * SMA_H;                // 3 x 16KB ring
    const int tid = threadIdx.x, lane = tid & 31, wid = tid >> 5;
    const int strip = blockIdx.x, ochalf = blockIdx.y, n_img = blockIdx.z;
    const int Q0 = strip * 128;
    const int oc0 = ochalf * 128;
    const int Mb = (wid & 1) * 64;     // warp M base
    const int Nb = (wid >> 1) * 64;    // warp N base

    float acc[4][8][4];
#pragma unroll
    for (int i = 0; i < 4; i++)
#pragma unroll
        for (int j = 0; j < 8; j++)
#pragma unroll
            for (int k = 0; k < 4; k++) acc[i][j][k] = 0.f;

    auto stageA = [&](int half) {
        const __half* src = g_xh + ((size_t)n_img * QP + Q0) * CIN + half * 64;
        const uint32_t d0 = sbA + half * SMA_H;
#pragma unroll
        for (int it = 0; it < 16; it++) {
            int idx = tid + it * 128;
            int row = idx >> 3, t = idx & 7;
            cpa16(d0 + swz(row, t), src + (size_t)row * CIN + t * 8);
        }
    };
    auto stageB = [&](int chunk, int b) {
        const int tap = (chunk < 9) ? chunk : chunk - 9;
        const int half = (chunk < 9) ? 0 : 1;
        const __half* src = g_wh + ((size_t)tap * COUT + oc0) * CIN + half * 64;
        const uint32_t d0 = sbB + b * SMB;
#pragma unroll
        for (int it = 0; it < 8; it++) {
            int idx = tid + it * 128;
            int row = idx >> 3, t = idx & 7;
            cpa16(d0 + swz(row, t), src + (size_t)row * CIN + t * 8);
        }
    };

    // prologue: G0 = {A half0, B0}, G1 = {B1}
    stageA(0);
    stageB(0, 0);
    asm volatile("cp.async.commit_group;" ::: "memory");
    stageB(1, 1);
    asm volatile("cp.async.commit_group;" ::: "memory");

    for (int ch = 0; ch < 18; ch++) {
        if (ch < 17) asm volatile("cp.async.wait_group 1;" ::: "memory");
        else         asm volatile("cp.async.wait_group 0;" ::: "memory");
        __syncthreads();
        if (ch + 2 < 18) {
            stageB(ch + 2, (ch + 2) % 3);
            if (ch == 0) stageA(1);   // A half1 prefetch; needed at ch=9
            asm volatile("cp.async.commit_group;" ::: "memory");
        }

        const int tap = (ch < 9) ? ch : ch - 9;
        const int offq = (tap / 3) * 58 + (tap % 3);
        const uint32_t abase = sbA + ((ch < 9) ? 0 : SMA_H);
        const uint32_t bbase = sbB + (ch % 3) * SMB;

#pragma unroll
        for (int ks = 0; ks < 4; ks++) {
            uint32_t af[4][4], bf[4][4];
            const int ta = ks * 2 + (lane >> 4);
            const int tb = ks * 2 + ((lane >> 3) & 1);
#pragma unroll
            for (int mt = 0; mt < 4; mt++) {
                int row = offq + Mb + mt * 16 + (lane & 15);
                ldsm4(af[mt], abase + swz(row, ta));
            }
#pragma unroll
            for (int np = 0; np < 4; np++) {
                int row = Nb + np * 16 + (lane & 7) + ((lane >> 4) << 3);
                ldsm4(bf[np], bbase + swz(row, tb));
            }
#pragma unroll
            for (int mt = 0; mt < 4; mt++)
#pragma unroll
                for (int np = 0; np < 4; np++) {
                    mma16816(acc[mt][np * 2],     af[mt], bf[np]);
                    mma16816(acc[mt][np * 2 + 1], af[mt], bf[np] + 2);
                }
        }
    }

    // ---- epilogue: registers -> NCHW out ----
#pragma unroll
    for (int mt = 0; mt < 4; mt++) {
        const int m0 = Mb + mt * 16 + (lane >> 2);
#pragma unroll
        for (int nt = 0; nt < 8; nt++) {
            const int n0 = oc0 + Nb + nt * 8 + (lane & 3) * 2;
            const size_t ob = ((size_t)n_img * COUT + n0) * 3136;
            int q = Q0 + m0;
            int y = q / 58, x = q - y * 58;
            if (y < 56 && x < 56) {
                size_t o = ob + y * 56 + x;
                out[o]        = acc[mt][nt][0];
                out[o + 3136] = acc[mt][nt][1];
            }
            q += 8;
            y = q / 58; x = q - y * 58;
            if (y < 56 && x < 56) {
                size_t o = ob + y * 56 + x;
                out[o]        = acc[mt][nt][2];
                out[o + 3136] = acc[mt][nt][3];
            }
        }
    }
}

// ---------------- launch ----------------
extern "C" void kernel_launch(void* const* d_in, const int* in_sizes, int n_in,
                              void* d_out, int out_size) {
    const float* x = (const float*)d_in[0];   // [32,128,56,56]
    const float* w = (const float*)d_in[1];   // [256,128,3,3]
    float* out = (float*)d_out;               // [32,256,56,56]

    static bool attr_set = false;
    if (!attr_set) {
        cudaFuncSetAttribute(conv_mma, cudaFuncAttributeMaxDynamicSharedMemorySize, SM_TOTAL);
        attr_set = true;
    }

    prep_w<<<COUT, 128>>>(w);
    prep_x<<<dim3(58, NIMG), 256>>>(x);
    conv_mma<<<dim3(NSTRIP, 2, NIMG), 128, SM_TOTAL>>>(out);
}